// round 1
// baseline (speedup 1.0000x reference)
#include <cuda_runtime.h>

// UpsampleInterp: [1, 80, 96, 112, 16] f32 -> [1, 160, 192, 224, 16] f32
// 2x multilinear upsampling per spatial axis with edge clamp.
//
// Strategy: one thread per (input voxel, channel quad). Each thread loads the
// 2x2x2 clamped corner neighborhood (8 x float4 = 128 B) and writes the 8
// output voxels it generates (8 x float4 = 128 B). Input (55 MB) lives in L2;
// output (440 MB) is written with streaming stores to avoid evicting it.

#define DD 80
#define HH 96
#define WW 112
// C = 16 floats = 4 float4 quads per voxel

__device__ __forceinline__ float4 f4_avg2(float4 a, float4 b) {
    return make_float4(0.5f * (a.x + b.x), 0.5f * (a.y + b.y),
                       0.5f * (a.z + b.z), 0.5f * (a.w + b.w));
}
__device__ __forceinline__ float4 f4_avg4(float4 a, float4 b, float4 c, float4 d) {
    return make_float4(0.25f * (a.x + b.x + c.x + d.x),
                       0.25f * (a.y + b.y + c.y + d.y),
                       0.25f * (a.z + b.z + c.z + d.z),
                       0.25f * (a.w + b.w + c.w + d.w));
}
__device__ __forceinline__ float4 f4_avg8(float4 a, float4 b, float4 c, float4 d,
                                          float4 e, float4 f, float4 g, float4 h) {
    return make_float4(0.125f * (a.x + b.x + c.x + d.x + e.x + f.x + g.x + h.x),
                       0.125f * (a.y + b.y + c.y + d.y + e.y + f.y + g.y + h.y),
                       0.125f * (a.z + b.z + c.z + d.z + e.z + f.z + g.z + h.z),
                       0.125f * (a.w + b.w + c.w + d.w + e.w + f.w + g.w + h.w));
}

__global__ void __launch_bounds__(256)
upsample_2x_kernel(const float4* __restrict__ in, float4* __restrict__ out) {
    int tid = blockIdx.x * 256 + threadIdx.x;
    // total threads = DD*HH*WW*4 = 3,440,640 (grid sized exactly)

    int c4 = tid & 3;
    int t  = tid >> 2;
    int x  = t % WW;
    int t2 = t / WW;
    int y  = t2 % HH;
    int z  = t2 / HH;

    int xp = min(x + 1, WW - 1);
    int yp = min(y + 1, HH - 1);
    int zp = min(z + 1, DD - 1);

    // input float4 index
    #define IIDX(zz, yy, xx) ((((zz) * HH + (yy)) * WW + (xx)) * 4 + c4)
    float4 v000 = in[IIDX(z,  y,  x )];
    float4 v001 = in[IIDX(z,  y,  xp)];
    float4 v010 = in[IIDX(z,  yp, x )];
    float4 v011 = in[IIDX(z,  yp, xp)];
    float4 v100 = in[IIDX(zp, y,  x )];
    float4 v101 = in[IIDX(zp, y,  xp)];
    float4 v110 = in[IIDX(zp, yp, x )];
    float4 v111 = in[IIDX(zp, yp, xp)];
    #undef IIDX

    int zo = 2 * z, yo = 2 * y, xo = 2 * x;
    // output float4 index (dims 2*DD x 2*HH x 2*WW)
    #define OIDX(zz, yy, xx) ((((zz) * (2 * HH) + (yy)) * (2 * WW) + (xx)) * 4 + c4)

    __stcs(&out[OIDX(zo,     yo,     xo    )], v000);
    __stcs(&out[OIDX(zo,     yo,     xo + 1)], f4_avg2(v000, v001));
    __stcs(&out[OIDX(zo,     yo + 1, xo    )], f4_avg2(v000, v010));
    __stcs(&out[OIDX(zo,     yo + 1, xo + 1)], f4_avg4(v000, v001, v010, v011));
    __stcs(&out[OIDX(zo + 1, yo,     xo    )], f4_avg2(v000, v100));
    __stcs(&out[OIDX(zo + 1, yo,     xo + 1)], f4_avg4(v000, v001, v100, v101));
    __stcs(&out[OIDX(zo + 1, yo + 1, xo    )], f4_avg4(v000, v010, v100, v110));
    __stcs(&out[OIDX(zo + 1, yo + 1, xo + 1)], f4_avg8(v000, v001, v010, v011,
                                                       v100, v101, v110, v111));
    #undef OIDX
}

extern "C" void kernel_launch(void* const* d_in, const int* in_sizes, int n_in,
                              void* d_out, int out_size) {
    const float4* in  = (const float4*)d_in[0];
    float4*       out = (float4*)d_out;

    const int total_threads = DD * HH * WW * 4;  // 3,440,640
    const int block = 256;
    const int grid  = total_threads / block;     // 13,440 exactly

    upsample_2x_kernel<<<grid, block>>>(in, out);
}